// round 8
// baseline (speedup 1.0000x reference)
#include <cuda_runtime.h>

#define N    8192
#define NZ   256
#define NC   128
#define TPB  256
#define RPB  4                 // rows per block in update (measured best)
#define SPLZ 4                 // split-K for z
#define SPLR 4                 // split-K for readout
#define NUPD (N / RPB)         // 2048 update blocks
#define NRO  ((NZ + NC) * SPLR) // 1536 readout blocks

__device__ float g_r[N];                   // r = tanh(x+b)
__device__ float g_zpart[SPLZ][NZ];        // split partials of z = W_rz @ r
__device__ float g_ropart[SPLR][NZ + NC];  // split partials of readout matvecs
__device__ int   g_slice_done[SPLR];       // update blocks done per r_new quarter
__device__ int   g_ro_count;               // last-block ticket for readout combine

__device__ __forceinline__ float warp_red(float v) {
    #pragma unroll
    for (int o = 16; o; o >>= 1) v += __shfl_down_sync(0xffffffffu, v, o);
    return v;
}

__device__ __forceinline__ float block_reduce(float v) {
    __shared__ float sm[TPB / 32];
    int lane = threadIdx.x & 31, wid = threadIdx.x >> 5;
    v = warp_red(v);
    if (lane == 0) sm[wid] = v;
    __syncthreads();
    if (wid == 0) {
        v = (lane < TPB / 32) ? sm[lane] : 0.0f;
        v = warp_red(v);
    }
    return v;  // valid in thread 0
}

__device__ __forceinline__ void block_reduceN(float* s) {
    __shared__ float sm[RPB][TPB / 32];
    int lane = threadIdx.x & 31, wid = threadIdx.x >> 5;
    #pragma unroll
    for (int k = 0; k < RPB; k++) {
        float v = warp_red(s[k]);
        if (lane == 0) sm[k][wid] = v;
    }
    __syncthreads();
    if (wid == 0) {
        #pragma unroll
        for (int k = 0; k < RPB; k++) {
            float v = (lane < TPB / 32) ? sm[k][lane] : 0.0f;
            s[k] = warp_red(v);   // valid in lane 0
        }
    }
}

__device__ __forceinline__ float dot4(float4 w, float4 v, float s) {
    return fmaf(w.x, v.x, fmaf(w.y, v.y, fmaf(w.z, v.z, fmaf(w.w, v.w, s))));
}

__device__ __forceinline__ float4 tanh4(float4 a, float4 bb) {
    return make_float4(tanhf(a.x + bb.x), tanhf(a.y + bb.y),
                       tanhf(a.z + bb.z), tanhf(a.w + bb.w));
}

// ── Kernel A: fused r = tanh(x+b) AND z partials. grid = NZ*SPLZ = 1024. ──
// Each block handles one (row, part): loads its W slice + x,b slice, computes
// the r slice locally (tanh hidden under W loads), dots, reduces.
// row==0 blocks also publish their r slice to g_r. Block 0 resets counters.
__global__ void k_rz(const float* __restrict__ x, const float* __restrict__ b,
                     const float* __restrict__ W_rz) {
    int bid = blockIdx.x;
    int row = bid >> 2, part = bid & 3;
    int t = threadIdx.x;
    if (bid == 0 && t < SPLR + 1) {
        if (t < SPLR) g_slice_done[t] = 0;
        else g_ro_count = 0;
    }
    const int C4 = N / 4 / SPLZ;  // 512 float4 per part
    const int base = part * C4;
    const float4* W4 = reinterpret_cast<const float4*>(W_rz + (size_t)row * N) + base;
    const float4* x4 = reinterpret_cast<const float4*>(x) + base;
    const float4* b4 = reinterpret_cast<const float4*>(b) + base;

    float4 w0 = __ldcs(&W4[t]);
    float4 w1 = __ldcs(&W4[t + TPB]);
    float4 r0 = tanh4(x4[t], b4[t]);
    float4 r1 = tanh4(x4[t + TPB], b4[t + TPB]);
    if (row == 0) {
        reinterpret_cast<float4*>(g_r)[base + t] = r0;
        reinterpret_cast<float4*>(g_r)[base + t + TPB] = r1;
    }
    float s = dot4(w0, r0, 0.0f);
    s = dot4(w1, r1, s);
    s = block_reduce(s);
    if (t == 0) g_zpart[part][row] = s;
}

// ── Kernel B: fused update + readout. grid = NUPD + NRO = 3584. ──
__global__ void k_main(const float* __restrict__ x,
                       const float* __restrict__ b,
                       const float* __restrict__ eps,
                       const float* __restrict__ c,
                       const float* __restrict__ W_rr,
                       const float* __restrict__ W_zr,
                       const float* __restrict__ W_cr,
                       const float* __restrict__ W_epsr,
                       const float* __restrict__ W_rz,
                       const float* __restrict__ W_rc,
                       const float* __restrict__ z_tilde,
                       float* __restrict__ out) {
    if (blockIdx.x < NUPD) {
        // ---- update path: RPB=4 rows per block (R4 measured-best shape) ----
        int row0 = blockIdx.x * RPB;
        const float4* r4 = reinterpret_cast<const float4*>(g_r);
        const float4* W0 = reinterpret_cast<const float4*>(W_rr + (size_t)row0 * N);
        const size_t RS = N / 4;

        float s[RPB] = {0.f, 0.f, 0.f, 0.f};
        #pragma unroll 2
        for (int j = threadIdx.x; j < N / 4; j += TPB) {
            float4 rv = r4[j];
            #pragma unroll
            for (int k = 0; k < RPB; k++) {
                float4 w = __ldcs(&W0[(size_t)k * RS + j]);
                s[k] = dot4(w, rv, s[k]);
            }
        }

        if (threadIdx.x < NZ / 4) {
            int j = threadIdx.x;
            float4 ev = reinterpret_cast<const float4*>(eps)[j];
            float4 zv = make_float4(0.f, 0.f, 0.f, 0.f);
            #pragma unroll
            for (int p = 0; p < SPLZ; p++) {
                float4 a = reinterpret_cast<const float4*>(g_zpart[p])[j];
                zv.x += a.x; zv.y += a.y; zv.z += a.z; zv.w += a.w;
            }
            #pragma unroll
            for (int k = 0; k < RPB; k++) {
                const float4* We = reinterpret_cast<const float4*>(W_epsr + (size_t)(row0 + k) * NZ);
                const float4* Wz = reinterpret_cast<const float4*>(W_zr   + (size_t)(row0 + k) * NZ);
                float4 we = __ldcs(&We[j]);
                float4 wz = __ldcs(&Wz[j]);
                s[k] = dot4(we, ev, s[k]);
                s[k] = dot4(wz, zv, s[k]);
            }
        }
        if (threadIdx.x < NC / 4) {
            int j = threadIdx.x;
            float4 cv = reinterpret_cast<const float4*>(c)[j];
            #pragma unroll
            for (int k = 0; k < RPB; k++) {
                const float4* Wc = reinterpret_cast<const float4*>(W_cr + (size_t)(row0 + k) * NC);
                float4 wc = __ldcs(&Wc[j]);
                s[k] = dot4(wc, cv, s[k]);
            }
        }

        block_reduceN(s);
        if (threadIdx.x == 0) {
            #pragma unroll
            for (int k = 0; k < RPB; k++) {
                int row = row0 + k;
                float xi = x[row];
                float xn = xi + 0.1f * (-xi + s[k]);   // dt=0.1, tau=1
                out[row] = xn;
                out[N + row] = tanhf(xn + b[row]);
            }
            // publish: this block's rows belong to quarter (blockIdx.x >> 9)
            __threadfence();
            atomicAdd(&g_slice_done[blockIdx.x >> 9], 1);
        }
    } else {
        // ---- readout path: block per (row, part), waits for its r_new quarter ----
        int bi   = blockIdx.x - NUPD;   // 0 .. NRO-1
        int row  = bi >> 2;             // SPLR == 4
        int part = bi & 3;
        // gate: quarter `part` of r_new is done when 512 update blocks reported
        if (threadIdx.x == 0) {
            while (atomicAdd(&g_slice_done[part], 0) < NUPD / SPLR) __nanosleep(64);
        }
        __syncthreads();
        __threadfence();

        const int C4 = N / 4 / SPLR;  // 512 float4 per part
        const float* Wrow = (row < NZ) ? (W_rz + (size_t)row * N)
                                       : (W_rc + (size_t)(row - NZ) * N);
        const float4* W4 = reinterpret_cast<const float4*>(Wrow) + part * C4;
        const float4* r4 = reinterpret_cast<const float4*>(out + N) + part * C4;  // r_new
        int t = threadIdx.x;
        float4 w0 = __ldcs(&W4[t]);
        float4 w1 = __ldcs(&W4[t + TPB]);
        float4 r0 = r4[t];
        float4 r1 = r4[t + TPB];
        float s = dot4(w0, r0, 0.0f);
        s = dot4(w1, r1, s);
        s = block_reduce(s);
        if (t == 0) g_ropart[part][row] = s;

        // last readout block combines (deterministic fixed-order sum)
        __threadfence();
        __syncthreads();
        __shared__ int isLast;
        if (threadIdx.x == 0) {
            int old = atomicAdd(&g_ro_count, 1);
            isLast = (old == NRO - 1);
        }
        __syncthreads();
        if (isLast) {
            __threadfence();
            for (int i = threadIdx.x; i < NZ + NC; i += TPB) {
                float v = 0.0f;
                #pragma unroll
                for (int p = 0; p < SPLR; p++) v += g_ropart[p][i];
                if (i < NZ) {
                    out[2 * N + i] = v;                           // z_new
                    out[2 * N + NZ + NC + i] = v - z_tilde[i];    // eps_new
                } else {
                    out[2 * N + NZ + (i - NZ)] = v;               // c_new
                }
            }
        }
    }
}

extern "C" void kernel_launch(void* const* d_in, const int* in_sizes, int n_in,
                              void* d_out, int out_size) {
    const float* x       = (const float*)d_in[0];
    const float* eps     = (const float*)d_in[1];
    const float* c       = (const float*)d_in[2];
    const float* z_tilde = (const float*)d_in[3];
    const float* W_rr    = (const float*)d_in[4];
    const float* W_zr    = (const float*)d_in[5];
    const float* W_cr    = (const float*)d_in[6];
    const float* W_epsr  = (const float*)d_in[7];
    const float* W_rz    = (const float*)d_in[8];
    const float* W_rc    = (const float*)d_in[9];
    const float* b       = (const float*)d_in[10];
    float* out = (float*)d_out;

    k_rz<<<NZ * SPLZ, TPB>>>(x, b, W_rz);
    k_main<<<NUPD + NRO, TPB>>>(x, b, eps, c, W_rr, W_zr, W_cr, W_epsr,
                                W_rz, W_rc, z_tilde, out);
}

// round 9
// speedup vs baseline: 1.0356x; 1.0356x over previous
#include <cuda_runtime.h>

#define N    8192
#define NZ   256
#define NC   128
#define TPB  256
#define RPB  4                  // rows per group (measured best)
#define GRP  2                  // sequential row-groups per update block
#define NBLK (N / RPB / GRP)    // 1024 update blocks, single wave
#define SPLZ 4                  // split-K for z
#define SPLR 4                  // split-K for readout
#define NRO  ((NZ + NC) * SPLR) // 1536 readout blocks

__device__ float g_r[N];                   // r = tanh(x+b)
__device__ float g_zpart[SPLZ][NZ];        // split partials of z = W_rz @ r
__device__ float g_ropart[SPLR][NZ + NC];  // split partials of readout matvecs
__device__ int   g_ro_count;               // last-block ticket for readout combine

__device__ __forceinline__ float warp_red(float v) {
    #pragma unroll
    for (int o = 16; o; o >>= 1) v += __shfl_down_sync(0xffffffffu, v, o);
    return v;
}

__device__ __forceinline__ float block_reduce(float v) {
    __shared__ float sm[TPB / 32];
    int lane = threadIdx.x & 31, wid = threadIdx.x >> 5;
    v = warp_red(v);
    if (lane == 0) sm[wid] = v;
    __syncthreads();
    if (wid == 0) {
        v = (lane < TPB / 32) ? sm[lane] : 0.0f;
        v = warp_red(v);
    }
    return v;  // valid in thread 0
}

__device__ __forceinline__ void block_reduceN(float* s) {
    __shared__ float sm[RPB][TPB / 32];
    int lane = threadIdx.x & 31, wid = threadIdx.x >> 5;
    #pragma unroll
    for (int k = 0; k < RPB; k++) {
        float v = warp_red(s[k]);
        if (lane == 0) sm[k][wid] = v;
    }
    __syncthreads();
    if (wid == 0) {
        #pragma unroll
        for (int k = 0; k < RPB; k++) {
            float v = (lane < TPB / 32) ? sm[k][lane] : 0.0f;
            s[k] = warp_red(v);   // valid in lane 0
        }
    }
}

__device__ __forceinline__ float dot4(float4 w, float4 v, float s) {
    return fmaf(w.x, v.x, fmaf(w.y, v.y, fmaf(w.z, v.z, fmaf(w.w, v.w, s))));
}

__device__ __forceinline__ float4 tanh4(float4 a, float4 bb) {
    return make_float4(tanhf(a.x + bb.x), tanhf(a.y + bb.y),
                       tanhf(a.z + bb.z), tanhf(a.w + bb.w));
}

// ── Kernel A: fused r = tanh(x+b) AND z partials. grid = NZ*SPLZ = 1024. ──
__global__ void k_rz(const float* __restrict__ x, const float* __restrict__ b,
                     const float* __restrict__ W_rz) {
    int bid = blockIdx.x;
    int row = bid >> 2, part = bid & 3;
    int t = threadIdx.x;
    if (bid == 0 && t == 0) g_ro_count = 0;
    const int C4 = N / 4 / SPLZ;  // 512 float4 per part
    const int base = part * C4;
    const float4* W4 = reinterpret_cast<const float4*>(W_rz + (size_t)row * N) + base;
    const float4* x4 = reinterpret_cast<const float4*>(x) + base;
    const float4* b4 = reinterpret_cast<const float4*>(b) + base;

    float4 w0 = __ldcs(&W4[t]);
    float4 w1 = __ldcs(&W4[t + TPB]);
    float4 r0 = tanh4(x4[t], b4[t]);
    float4 r1 = tanh4(x4[t + TPB], b4[t + TPB]);
    if (row == 0) {
        reinterpret_cast<float4*>(g_r)[base + t] = r0;
        reinterpret_cast<float4*>(g_r)[base + t + TPB] = r1;
    }
    float s = dot4(w0, r0, 0.0f);
    s = dot4(w1, r1, s);
    s = block_reduce(s);
    if (t == 0) g_zpart[part][row] = s;
}

// ── Kernel B: fused Euler update. grid = NBLK = 1024 (one resident wave),
// each block sequentially handles row-groups blockIdx.x and blockIdx.x+1024. ──
__global__ void __launch_bounds__(TPB) k_update(
                         const float* __restrict__ x,
                         const float* __restrict__ b,
                         const float* __restrict__ eps,
                         const float* __restrict__ c,
                         const float* __restrict__ W_rr,
                         const float* __restrict__ W_zr,
                         const float* __restrict__ W_cr,
                         const float* __restrict__ W_epsr,
                         float* __restrict__ out) {
    const float4* r4 = reinterpret_cast<const float4*>(g_r);
    const size_t RS = N / 4;  // row stride in float4

    // preload small shared operands once per block
    float4 ev = make_float4(0.f,0.f,0.f,0.f), zv = make_float4(0.f,0.f,0.f,0.f);
    float4 cv = make_float4(0.f,0.f,0.f,0.f);
    if (threadIdx.x < NZ / 4) {
        int j = threadIdx.x;
        ev = reinterpret_cast<const float4*>(eps)[j];
        #pragma unroll
        for (int p = 0; p < SPLZ; p++) {
            float4 a = reinterpret_cast<const float4*>(g_zpart[p])[j];
            zv.x += a.x; zv.y += a.y; zv.z += a.z; zv.w += a.w;
        }
    }
    if (threadIdx.x < NC / 4)
        cv = reinterpret_cast<const float4*>(c)[threadIdx.x];

    #pragma unroll
    for (int g = 0; g < GRP; g++) {
        int row0 = (blockIdx.x + g * NBLK) * RPB;
        const float4* W0 = reinterpret_cast<const float4*>(W_rr + (size_t)row0 * N);

        float s[RPB] = {0.f, 0.f, 0.f, 0.f};
        #pragma unroll 2
        for (int j = threadIdx.x; j < N / 4; j += TPB) {
            float4 rv = r4[j];
            #pragma unroll
            for (int k = 0; k < RPB; k++) {
                float4 w = __ldcs(&W0[(size_t)k * RS + j]);
                s[k] = dot4(w, rv, s[k]);
            }
        }

        if (threadIdx.x < NZ / 4) {
            int j = threadIdx.x;
            #pragma unroll
            for (int k = 0; k < RPB; k++) {
                const float4* We = reinterpret_cast<const float4*>(W_epsr + (size_t)(row0 + k) * NZ);
                const float4* Wz = reinterpret_cast<const float4*>(W_zr   + (size_t)(row0 + k) * NZ);
                float4 we = __ldcs(&We[j]);
                float4 wz = __ldcs(&Wz[j]);
                s[k] = dot4(we, ev, s[k]);
                s[k] = dot4(wz, zv, s[k]);
            }
        }
        if (threadIdx.x < NC / 4) {
            int j = threadIdx.x;
            #pragma unroll
            for (int k = 0; k < RPB; k++) {
                const float4* Wc = reinterpret_cast<const float4*>(W_cr + (size_t)(row0 + k) * NC);
                float4 wc = __ldcs(&Wc[j]);
                s[k] = dot4(wc, cv, s[k]);
            }
        }

        block_reduceN(s);
        if (threadIdx.x == 0) {
            #pragma unroll
            for (int k = 0; k < RPB; k++) {
                int row = row0 + k;
                float xi = x[row];
                float xn = xi + 0.1f * (-xi + s[k]);   // dt=0.1, tau=1
                out[row] = xn;
                out[N + row] = tanhf(xn + b[row]);
            }
        }
        if (g + 1 < GRP) __syncthreads();   // reuse of block_reduceN smem
    }
}

// ── Kernel C: readout partials on r_new + last-block combine. grid = 1536. ──
__global__ void k_readout(const float* __restrict__ W_rz,
                          const float* __restrict__ W_rc,
                          const float* __restrict__ z_tilde,
                          float* __restrict__ out) {
    int row  = blockIdx.x >> 2;        // SPLR == 4
    int part = blockIdx.x & 3;
    const int C4 = N / 4 / SPLR;       // 512 float4 per part
    const float* Wrow = (row < NZ) ? (W_rz + (size_t)row * N)
                                   : (W_rc + (size_t)(row - NZ) * N);
    const float4* W4 = reinterpret_cast<const float4*>(Wrow) + part * C4;
    const float4* r4 = reinterpret_cast<const float4*>(out + N) + part * C4;  // r_new
    int t = threadIdx.x;
    float4 w0 = __ldcs(&W4[t]);
    float4 w1 = __ldcs(&W4[t + TPB]);
    float4 r0 = r4[t];
    float4 r1 = r4[t + TPB];
    float s = dot4(w0, r0, 0.0f);
    s = dot4(w1, r1, s);
    s = block_reduce(s);
    if (t == 0) g_ropart[part][row] = s;

    // last-block combine (deterministic fixed-order sum)
    __threadfence();
    __syncthreads();
    __shared__ int isLast;
    if (threadIdx.x == 0) {
        int old = atomicAdd(&g_ro_count, 1);
        isLast = (old == NRO - 1);
    }
    __syncthreads();
    if (isLast) {
        __threadfence();
        for (int i = threadIdx.x; i < NZ + NC; i += TPB) {
            float v = 0.0f;
            #pragma unroll
            for (int p = 0; p < SPLR; p++) v += g_ropart[p][i];
            if (i < NZ) {
                out[2 * N + i] = v;                           // z_new
                out[2 * N + NZ + NC + i] = v - z_tilde[i];    // eps_new
            } else {
                out[2 * N + NZ + (i - NZ)] = v;               // c_new
            }
        }
    }
}

extern "C" void kernel_launch(void* const* d_in, const int* in_sizes, int n_in,
                              void* d_out, int out_size) {
    const float* x       = (const float*)d_in[0];
    const float* eps     = (const float*)d_in[1];
    const float* c       = (const float*)d_in[2];
    const float* z_tilde = (const float*)d_in[3];
    const float* W_rr    = (const float*)d_in[4];
    const float* W_zr    = (const float*)d_in[5];
    const float* W_cr    = (const float*)d_in[6];
    const float* W_epsr  = (const float*)d_in[7];
    const float* W_rz    = (const float*)d_in[8];
    const float* W_rc    = (const float*)d_in[9];
    const float* b       = (const float*)d_in[10];
    float* out = (float*)d_out;

    k_rz<<<NZ * SPLZ, TPB>>>(x, b, W_rz);
    k_update<<<NBLK, TPB>>>(x, b, eps, c, W_rr, W_zr, W_cr, W_epsr, out);
    k_readout<<<NRO, TPB>>>(W_rz, W_rc, z_tilde, out);
}

// round 10
// speedup vs baseline: 1.0631x; 1.0265x over previous
#include <cuda_runtime.h>

#define N    8192
#define NZ   256
#define NC   128
#define TPB  256
#define RPB  4                  // rows per block in k_update (measured best)
#define SPLZ 4                  // split-K for k_z (measured best)
#define SPLR 4                  // split-K for k_readout (measured best)
#define NRO  ((NZ + NC) * SPLR) // 1536 readout blocks

__device__ float g_r[N];                   // r = tanh(x+b)
__device__ float g_zpart[SPLZ][NZ];        // split partials of z = W_rz @ r
__device__ float g_ropart[SPLR][NZ + NC];  // split partials of readout matvecs
__device__ int   g_ro_count;               // last-block ticket for readout combine

__device__ __forceinline__ float warp_red(float v) {
    #pragma unroll
    for (int o = 16; o; o >>= 1) v += __shfl_down_sync(0xffffffffu, v, o);
    return v;
}

__device__ __forceinline__ float block_reduce(float v) {
    __shared__ float sm[TPB / 32];
    int lane = threadIdx.x & 31, wid = threadIdx.x >> 5;
    v = warp_red(v);
    if (lane == 0) sm[wid] = v;
    __syncthreads();
    if (wid == 0) {
        v = (lane < TPB / 32) ? sm[lane] : 0.0f;
        v = warp_red(v);
    }
    return v;  // valid in thread 0
}

__device__ __forceinline__ void block_reduceN(float* s) {
    __shared__ float sm[RPB][TPB / 32];
    int lane = threadIdx.x & 31, wid = threadIdx.x >> 5;
    #pragma unroll
    for (int k = 0; k < RPB; k++) {
        float v = warp_red(s[k]);
        if (lane == 0) sm[k][wid] = v;
    }
    __syncthreads();
    if (wid == 0) {
        #pragma unroll
        for (int k = 0; k < RPB; k++) {
            float v = (lane < TPB / 32) ? sm[k][lane] : 0.0f;
            s[k] = warp_red(v);   // valid in lane 0
        }
    }
}

__device__ __forceinline__ float dot4(float4 w, float4 v, float s) {
    return fmaf(w.x, v.x, fmaf(w.y, v.y, fmaf(w.z, v.z, fmaf(w.w, v.w, s))));
}

// ── Kernel 1: r = tanh(x + b), computed ONCE; also reset the readout ticket. ──
__global__ void k_rate(const float* __restrict__ x, const float* __restrict__ b) {
    int i = blockIdx.x * blockDim.x + threadIdx.x;
    if (i < N) g_r[i] = tanhf(x[i] + b[i]);
    if (i == 0) g_ro_count = 0;
}

// ── Kernel 2: z partials. grid = NZ*SPLZ = 1024; 2 load-pairs per thread. ──
__global__ void k_z(const float* __restrict__ W_rz) {
    int row  = blockIdx.x >> 2;        // SPLZ == 4
    int part = blockIdx.x & 3;
    const int C4 = N / 4 / SPLZ;       // 512 float4 per part
    const float4* W4 = reinterpret_cast<const float4*>(W_rz + (size_t)row * N) + part * C4;
    const float4* r4 = reinterpret_cast<const float4*>(g_r) + part * C4;
    int t = threadIdx.x;
    float4 w0 = __ldcs(&W4[t]);
    float4 w1 = __ldcs(&W4[t + TPB]);
    float4 r0 = r4[t];
    float4 r1 = r4[t + TPB];
    float s = dot4(w0, r0, 0.0f);
    s = dot4(w1, r1, s);
    s = block_reduce(s);
    if (t == 0) g_zpart[part][row] = s;
}

// ── Kernel 3: fused Euler update, RPB=4 rows per block, grid = 2048. ──
__global__ void k_update(const float* __restrict__ x,
                         const float* __restrict__ b,
                         const float* __restrict__ eps,
                         const float* __restrict__ c,
                         const float* __restrict__ W_rr,
                         const float* __restrict__ W_zr,
                         const float* __restrict__ W_cr,
                         const float* __restrict__ W_epsr,
                         float* __restrict__ out) {
    int row0 = blockIdx.x * RPB;
    const float4* r4 = reinterpret_cast<const float4*>(g_r);
    const float4* W0 = reinterpret_cast<const float4*>(W_rr + (size_t)row0 * N);
    const size_t RS = N / 4;  // row stride in float4

    float s[RPB] = {0.f, 0.f, 0.f, 0.f};
    #pragma unroll 2
    for (int j = threadIdx.x; j < N / 4; j += TPB) {
        float4 rv = r4[j];
        #pragma unroll
        for (int k = 0; k < RPB; k++) {
            float4 w = __ldcs(&W0[(size_t)k * RS + j]);
            s[k] = dot4(w, rv, s[k]);
        }
    }

    // tails: W_epsr @ eps, W_zr @ z, W_cr @ c
    if (threadIdx.x < NZ / 4) {
        int j = threadIdx.x;
        float4 ev = reinterpret_cast<const float4*>(eps)[j];
        float4 zv = make_float4(0.f, 0.f, 0.f, 0.f);
        #pragma unroll
        for (int p = 0; p < SPLZ; p++) {
            float4 a = reinterpret_cast<const float4*>(g_zpart[p])[j];
            zv.x += a.x; zv.y += a.y; zv.z += a.z; zv.w += a.w;
        }
        #pragma unroll
        for (int k = 0; k < RPB; k++) {
            const float4* We = reinterpret_cast<const float4*>(W_epsr + (size_t)(row0 + k) * NZ);
            const float4* Wz = reinterpret_cast<const float4*>(W_zr   + (size_t)(row0 + k) * NZ);
            float4 we = __ldcs(&We[j]);
            float4 wz = __ldcs(&Wz[j]);
            s[k] = dot4(we, ev, s[k]);
            s[k] = dot4(wz, zv, s[k]);
        }
    }
    if (threadIdx.x < NC / 4) {
        int j = threadIdx.x;
        float4 cv = reinterpret_cast<const float4*>(c)[j];
        #pragma unroll
        for (int k = 0; k < RPB; k++) {
            const float4* Wc = reinterpret_cast<const float4*>(W_cr + (size_t)(row0 + k) * NC);
            float4 wc = __ldcs(&Wc[j]);
            s[k] = dot4(wc, cv, s[k]);
        }
    }

    block_reduceN(s);
    if (threadIdx.x == 0) {
        #pragma unroll
        for (int k = 0; k < RPB; k++) {
            int row = row0 + k;
            float xi = x[row];
            float xn = xi + 0.1f * (-xi + s[k]);   // dt=0.1, tau=1
            out[row] = xn;
            out[N + row] = tanhf(xn + b[row]);
        }
    }
}

// ── Kernel 4: readout partials on r_new + last-block combine. grid = 1536. ──
__global__ void k_readout(const float* __restrict__ W_rz,
                          const float* __restrict__ W_rc,
                          const float* __restrict__ z_tilde,
                          float* __restrict__ out) {
    int row  = blockIdx.x >> 2;        // SPLR == 4
    int part = blockIdx.x & 3;
    const int C4 = N / 4 / SPLR;       // 512 float4 per part
    const float* Wrow = (row < NZ) ? (W_rz + (size_t)row * N)
                                   : (W_rc + (size_t)(row - NZ) * N);
    const float4* W4 = reinterpret_cast<const float4*>(Wrow) + part * C4;
    const float4* r4 = reinterpret_cast<const float4*>(out + N) + part * C4;  // r_new
    int t = threadIdx.x;
    float4 w0 = __ldcs(&W4[t]);
    float4 w1 = __ldcs(&W4[t + TPB]);
    float4 r0 = r4[t];
    float4 r1 = r4[t + TPB];
    float s = dot4(w0, r0, 0.0f);
    s = dot4(w1, r1, s);
    s = block_reduce(s);
    if (t == 0) g_ropart[part][row] = s;

    // last-block combine (deterministic fixed-order sum)
    __threadfence();
    __syncthreads();
    __shared__ int isLast;
    if (threadIdx.x == 0) {
        int old = atomicAdd(&g_ro_count, 1);
        isLast = (old == NRO - 1);
    }
    __syncthreads();
    if (isLast) {
        __threadfence();
        for (int i = threadIdx.x; i < NZ + NC; i += TPB) {
            float v = 0.0f;
            #pragma unroll
            for (int p = 0; p < SPLR; p++) v += g_ropart[p][i];
            if (i < NZ) {
                out[2 * N + i] = v;                           // z_new
                out[2 * N + NZ + NC + i] = v - z_tilde[i];    // eps_new
            } else {
                out[2 * N + NZ + (i - NZ)] = v;               // c_new
            }
        }
    }
}

extern "C" void kernel_launch(void* const* d_in, const int* in_sizes, int n_in,
                              void* d_out, int out_size) {
    const float* x       = (const float*)d_in[0];
    const float* eps     = (const float*)d_in[1];
    const float* c       = (const float*)d_in[2];
    const float* z_tilde = (const float*)d_in[3];
    const float* W_rr    = (const float*)d_in[4];
    const float* W_zr    = (const float*)d_in[5];
    const float* W_cr    = (const float*)d_in[6];
    const float* W_epsr  = (const float*)d_in[7];
    const float* W_rz    = (const float*)d_in[8];
    const float* W_rc    = (const float*)d_in[9];
    const float* b       = (const float*)d_in[10];
    float* out = (float*)d_out;

    k_rate<<<(N + TPB - 1) / TPB, TPB>>>(x, b);
    k_z<<<NZ * SPLZ, TPB>>>(W_rz);
    k_update<<<N / RPB, TPB>>>(x, b, eps, c, W_rr, W_zr, W_cr, W_epsr, out);
    k_readout<<<NRO, TPB>>>(W_rz, W_rc, z_tilde, out);
}